// round 14
// baseline (speedup 1.0000x reference)
#include <cuda_runtime.h>
#include <math.h>

#define T_LEN 1440
#define B_LEN 2048
#define N_RC  5
#define L_CH  16
#define N_CH  90      // 1440/16
#define WCH   3       // warm chunks (t < 48)

typedef unsigned long long u64;

__device__ float g_tzz[T_LEN * B_LEN];          // zero-state Tz trajectory
__device__ float g_d [(N_CH + 2) * 6 * B_LEN];  // per-chunk offsets (+pad)
__device__ float g_cs[N_CH * 6 * B_LEN];        // chunk-start states
__device__ float g_r0p[17 * 6];                 // row0(A^n), n=1..16 (from scan)
__device__ float g_e[16 * 5];                   // g*ri_i*m_i^s      (from scan)
__device__ u64   g_swab[64];                    // [2h]=w1a dup, [2h+1]=w1b dup
__device__ u64   g_sbw2[64];                    // [2h]=b1 dup,  [2h+1]=0.5*w2 dup
__device__ u64   g_cdup[3];                     // C0,C1,CB duplicated pairs
__device__ float g_c[27];                       // scalars + replay arrays

__device__ __forceinline__ float sp(float x) {
    if (x > 20.f)  return x;
    if (x < -20.f) return expf(x);
    return log1pf(expf(x));
}

__device__ __forceinline__ u64 pack2(float lo, float hi) {
    u64 r; asm("mov.b64 %0,{%1,%2};" : "=l"(r) : "f"(lo), "f"(hi)); return r;
}
__device__ __forceinline__ void unpack2(u64 v, float& lo, float& hi) {
    asm("mov.b64 {%0,%1},%2;" : "=f"(lo), "=f"(hi) : "l"(v));
}
__device__ __forceinline__ u64 fma2(u64 a, u64 b, u64 c) {
    u64 d; asm("fma.rn.f32x2 %0,%1,%2,%3;" : "=l"(d) : "l"(a), "l"(b), "l"(c)); return d;
}

struct P { float ri[N_RC], m[N_RC], kta[N_RC], ks[N_RC], alpha, g, gw; };

__device__ __forceinline__ void loadP(P& p,
    const float* rcR, const float* rcC, const float* winR,
    const float* paw, const float* par, const float* pcz)
{
    const float aw = 0.5f * sp(paw[0]);
    const float ar = 0.5f * sp(par[0]);
    float Rsum = 0.f;
    #pragma unroll
    for (int i = 0; i < N_RC; i++) {
        const float r = sp(rcR[i]) * 0.1f;
        const float c = sp(rcC[i]) * 1e-5f;
        const float a = (i < 4) ? aw : ar;
        p.ri[i] = r; Rsum += r;
        const float cd = c * 900.f;
        p.kta[i] = cd * r;
        p.m[i]   = 1.f - 2.f * cd * r;
        p.ks[i]  = cd * a;
    }
    const float win = (sp(winR[0]) + sp(winR[1])) * 0.5f;
    const float cz  = sp(pcz[0]) * 1e-5f;
    p.g     = cz * 900.f;
    p.alpha = 1.f - p.g * (Rsum + win);
    p.gw    = p.g * win;
}

__device__ __forceinline__ void hstep(const P& p, float x[6]) {
    float tz = x[0];
    float S = x[1] * p.ri[0];
    S = fmaf(x[2], p.ri[1], S);
    S = fmaf(x[3], p.ri[2], S);
    S = fmaf(x[4], p.ri[3], S);
    S = fmaf(x[5], p.ri[4], S);
    const float tznew = fmaf(p.alpha, tz, p.g * S);
    #pragma unroll
    for (int i = 0; i < N_RC; i++)
        x[1 + i] = fmaf(p.kta[i], tz, p.m[i] * x[1 + i]);
    x[0] = tznew;
}

// ---------------------------------------------------------------------------
// Precompute all scalar constants + packed weight tables. 1 block, 32 thr.
// ---------------------------------------------------------------------------
__global__ void k_pre(
    const float* __restrict__ rcR, const float* __restrict__ rcC,
    const float* __restrict__ winR,
    const float* __restrict__ W1, const float* __restrict__ B1,
    const float* __restrict__ W2, const float* __restrict__ B2,
    const float* __restrict__ pig, const float* __restrict__ phg,
    const float* __restrict__ pdg,
    const float* __restrict__ paw, const float* __restrict__ par,
    const float* __restrict__ pcz)
{
    const int tid = threadIdx.x;
    {
        const float wa = W1[2 * tid], wb = W1[2 * tid + 1];
        g_swab[2 * tid]     = pack2(wa, wa);
        g_swab[2 * tid + 1] = pack2(wb, wb);
        const float b1 = B1[tid], w2h = 0.5f * W2[tid];
        g_sbw2[2 * tid]     = pack2(b1, b1);
        g_sbw2[2 * tid + 1] = pack2(w2h, w2h);
    }
    if (tid == 0) {
        const float gi  = 0.1f * sp(pig[0]);
        const float gh  = 0.1f * sp(phg[0]);
        const float gd  = 0.5f * sp(pdg[0]);
        const float g   = sp(pcz[0]) * 1e-5f * 900.f;
        const float win = (sp(winR[0]) + sp(winR[1])) * 0.5f;
        const float aw  = 0.5f * sp(paw[0]);
        const float ar  = 0.5f * sp(par[0]);
        float Rsum = 0.f;
        #pragma unroll
        for (int i = 0; i < 5; i++) {
            const float r = sp(rcR[i]) * 0.1f;
            const float c = sp(rcC[i]) * 1e-5f;
            const float a = (i < 4) ? aw : ar;
            Rsum += r;
            const float cd = c * 900.f;
            g_c[7 + i]  = r;                   // ri
            g_c[12 + i] = 1.f - 2.f * cd * r;  // m
            g_c[17 + i] = cd * r;              // kta
            g_c[22 + i] = cd * a;              // ks
        }
        g_c[0] = g * win;      // gw
        g_c[1] = g * gd;       // gds
        g_c[2] = g * gh;       // ghs
        g_c[3] = g * gi;       // gis
        g_c[4] = g * gi;       // ggi
        g_c[5] = 1.f - g * (Rsum + win);  // alpha
        g_c[6] = g;
        float C0 = 0.f, C1 = 0.f, CB = B2[0];
        for (int h = 0; h < 32; h++) {
            const float w2h = 0.5f * W2[h];
            C0 = fmaf(w2h, W1[2 * h], C0);
            C1 = fmaf(w2h, W1[2 * h + 1], C1);
            CB = fmaf(w2h, B1[h], CB);
        }
        g_cdup[0] = pack2(C0, C0);
        g_cdup[1] = pack2(C1, C1);
        g_cdup[2] = pack2(CB, CB);
    }
}

// swizzled physical column for logical column L (compile-time at use sites)
#define SWC(L) ((((L) & ~3)) | (((((L) & 3)) + (((L) >> 5) & 3)) & 3))
#define SINR(L, R) s_in[SWC(L)][R]

// ---------------------------------------------------------------------------
// Phase A (fused drives + zero-state replay).
// 256 threads: staging (batched register LDG.128) -> MLP (all threads) ->
// replay (threads 0..63, one chain per batch row).
// ---------------------------------------------------------------------------
__global__ __launch_bounds__(256) void kA(const float* __restrict__ X)
{
    __shared__ float s_in[112][65];          // [physical col][row]
    __shared__ float u_s[64][17];            // per-(row,step) drive term
    __shared__ __align__(16) u64 swab[64];
    __shared__ __align__(16) u64 sbw2[64];
    __shared__ float s_c[5];
    __shared__ u64 s_cd[3];
    const int tid = threadIdx.x;
    if (tid < 64) { swab[tid] = g_swab[tid]; sbw2[tid] = g_sbw2[tid]; }
    else if (tid < 69)  s_c[tid - 64]  = g_c[tid - 64];
    else if (tid < 72)  s_cd[tid - 69] = g_cdup[tid - 69];

    const int j  = blockIdx.y;
    const bool warm = (j < WCH);
    const int t0 = j * L_CH;
    const int b0 = blockIdx.x * 64;

    // stage 64 rows x 28 float4: batched register loads (4 in flight), then STS
    {
        const int q  = tid & 31;
        const int rh = tid >> 5;             // 0..7
        if (q < 28) {
            const float4* src = reinterpret_cast<const float4*>(X)
                + (size_t)b0 * 2520 + (size_t)rh * 2520 + (size_t)j * 28 + q;
            const int qh = q >> 3;
            float* d0 = &s_in[4 * q + ((0 + qh) & 3)][rh];
            float* d1 = &s_in[4 * q + ((1 + qh) & 3)][rh];
            float* d2 = &s_in[4 * q + ((2 + qh) & 3)][rh];
            float* d3 = &s_in[4 * q + ((3 + qh) & 3)][rh];
            #pragma unroll
            for (int half = 0; half < 2; half++) {
                float4 r[4];
                #pragma unroll
                for (int k = 0; k < 4; k++)
                    r[k] = src[(size_t)(half * 4 + k) * 8 * 2520];
                #pragma unroll
                for (int k = 0; k < 4; k++) {
                    const int ro = 8 * (half * 4 + k);   // row offset
                    d0[ro] = r[k].x;
                    d1[ro] = r[k].y;
                    d2[ro] = r[k].z;
                    d3[ro] = r[k].w;
                }
            }
        }
    }
    __syncthreads();

    // MLP phase: thread -> (row = tid&63, timesteps 4*pg .. 4*pg+3)
    {
        const float gw  = s_c[0];
        const float gds = s_c[1];
        const float ghs = s_c[2];
        const float gis = s_c[3];
        const float ggi = s_c[4];
        const u64 c0d = s_cd[0], c1d = s_cd[1], cbd = s_cd[2];

        const int row = tid & 63;
        const int pg  = tid >> 6;            // 0..3
        u64 X0p[2], X1p[2], acc[2];
        float uu[4];
        #pragma unroll
        for (int pp = 0; pp < 2; pp++) {
            const int s0 = 4 * pg + 2 * pp, s1 = s0 + 1;
            const float ta0 = SINR(7 * s0 + 1, row), so0 = SINR(7 * s0 + 2, row);
            const float x00 = SINR(7 * s0 + 3, row), x10 = SINR(7 * s0 + 4, row);
            const float x20 = SINR(7 * s0 + 5, row), hv0 = SINR(7 * s0 + 6, row);
            const float ta1 = SINR(7 * s1 + 1, row), so1 = SINR(7 * s1 + 2, row);
            const float x01 = SINR(7 * s1 + 3, row), x11 = SINR(7 * s1 + 4, row);
            const float x21 = SINR(7 * s1 + 5, row), hv1 = SINR(7 * s1 + 6, row);
            X0p[pp] = pack2(x00, x01);
            X1p[pp] = pack2(x10, x11);
            acc[pp] = fma2(c0d, X0p[pp], fma2(c1d, X1p[pp], cbd));
            uu[2 * pp]     = fmaf(gw, ta0, fmaf(gds, so0, fmaf(ghs, hv0, gis * x20)));
            uu[2 * pp + 1] = fmaf(gw, ta1, fmaf(gds, so1, fmaf(ghs, hv1, gis * x21)));
        }
        #pragma unroll 8
        for (int h = 0; h < 32; h++) {
            const ulonglong2 wab = *reinterpret_cast<const ulonglong2*>(&swab[2 * h]);
            const ulonglong2 bw2 = *reinterpret_cast<const ulonglong2*>(&sbw2[2 * h]);
            #pragma unroll
            for (int pp = 0; pp < 2; pp++) {
                u64 z  = fma2(wab.x, X0p[pp], fma2(wab.y, X1p[pp], bw2.x));
                u64 za = z & 0x7FFFFFFF7FFFFFFFULL;      // |z| per half
                acc[pp] = fma2(bw2.y, za, acc[pp]);      // += 0.5*w2*|z|
            }
        }
        #pragma unroll
        for (int pp = 0; pp < 2; pp++) {
            float a0, a1; unpack2(acc[pp], a0, a1);
            const float sg0 = __fdividef(1.f, 1.f + __expf(-a0));
            const float sg1 = __fdividef(1.f, 1.f + __expf(-a1));
            uu[2 * pp]     = fmaf(ggi, sg0, uu[2 * pp]);
            uu[2 * pp + 1] = fmaf(ggi, sg1, uu[2 * pp + 1]);
        }
        #pragma unroll
        for (int k = 0; k < 4; k++) u_s[row][4 * pg + k] = uu[k];
    }
    __syncthreads();

    // Replay phase: threads 0..63, one sequential chain per batch row.
    if (tid < 64) {
        const float alpha = g_c[5];
        const float g     = g_c[6];
        float ri[5], m[5], kta[5], ks[5];
        #pragma unroll
        for (int i = 0; i < 5; i++) {
            ri[i]  = g_c[7 + i];
            m[i]   = g_c[12 + i];
            kta[i] = g_c[17 + i];
            ks[i]  = g_c[22 + i];
        }

        const int b = b0 + tid;
        float* pz = g_tzz + (unsigned)(t0 * B_LEN + b);   // + s*2048 (imm)
        float tm[5] = {0.f, 0.f, 0.f, 0.f, 0.f};
        float tz = 0.f;
        #pragma unroll
        for (int s = 0; s < 16; s++) {
            const float tac = SINR(7 * s + 1, tid);
            const float soc = SINR(7 * s + 2, tid);
            const float us  = u_s[tid][s];
            float tzc;
            if (warm) tzc = SINR(7 * s, tid);    // exogenous gt carry
            else      tzc = tz;
            float S = tm[0] * ri[0];
            S = fmaf(tm[1], ri[1], S);
            S = fmaf(tm[2], ri[2], S);
            S = fmaf(tm[3], ri[3], S);
            S = fmaf(tm[4], ri[4], S);
            const float tznew = fmaf(alpha, tzc, fmaf(g, S, us));
            pz[s * B_LEN] = tznew;
            const float tpz = tac + tzc;
            #pragma unroll
            for (int i = 0; i < 5; i++)
                tm[i] = fmaf(kta[i], tpz, fmaf(ks[i], soc, m[i] * tm[i]));
            tz = tznew;
        }
        float* pd = g_d + (unsigned)(j * 6 * B_LEN + b);  // + i*2048 (imm)
        if (!warm) pd[0] = tz;
        #pragma unroll
        for (int i = 0; i < 5; i++) pd[(1 + i) * B_LEN] = tm[i];
    }
}

// ---------------------------------------------------------------------------
// Scan over chunks, 4-chunk double-buffered prefetch. Also emits the A-power
// tables to global (block 0) for k_emit.
// ---------------------------------------------------------------------------
__global__ __launch_bounds__(64) void k_scan(
    const float* __restrict__ X,
    const float* __restrict__ rcR, const float* __restrict__ rcC,
    const float* __restrict__ winR,
    const float* __restrict__ paw, const float* __restrict__ par,
    const float* __restrict__ pcz)
{
    __shared__ float sA[36];
    __shared__ float sm16[5], se15[5];
    const int tid = threadIdx.x;
    if (tid < 7) {
        P p; loadP(p, rcR, rcC, winR, paw, par, pcz);
        if (tid < 6) {
            float x[6] = {0.f, 0.f, 0.f, 0.f, 0.f, 0.f};
            x[tid] = 1.f;
            for (int n = 1; n <= L_CH; n++) {
                hstep(p, x);
                if (blockIdx.x == 0) g_r0p[n * 6 + tid] = x[0];
            }
            #pragma unroll
            for (int i = 0; i < 6; i++) sA[i * 6 + tid] = x[i];
        } else {
            float mp[5] = {1.f, 1.f, 1.f, 1.f, 1.f};
            for (int s = 0; s < L_CH; s++) {
                #pragma unroll
                for (int i = 0; i < 5; i++) {
                    const float e = p.g * p.ri[i] * mp[i];
                    if (blockIdx.x == 0) g_e[s * 5 + i] = e;
                    if (s == 15) se15[i] = e;
                    mp[i] *= p.m[i];
                }
            }
            #pragma unroll
            for (int i = 0; i < 5; i++) sm16[i] = mp[i];
        }
    }

    const int b = blockIdx.x * 64 + tid;

    // prefetch warm d's and initial values
    const float* pdw = g_d + (unsigned)b;
    float wd[15];
    #pragma unroll
    for (int j = 0; j < WCH; j++)
        #pragma unroll
        for (int i = 0; i < 5; i++)
            wd[j * 5 + i] = pdw[(j * 6 + 1 + i) * B_LEN];
    const float gt0   = X[(size_t)b * (T_LEN * 7)];
    const float ta0   = X[(size_t)b * (T_LEN * 7) + 1];
    const float tzz47 = g_tzz[(unsigned)(47 * B_LEN + b)];

    // preload batch 0 (chunks 3..6)
    float buf[2][24];
    const float* pd = g_d + (unsigned)(WCH * 6 * B_LEN + b);
    #pragma unroll
    for (int q = 0; q < 24; q++) buf[0][q] = pd[q * B_LEN];

    __syncthreads();
    float A[36];
    #pragma unroll
    for (int i = 0; i < 36; i++) A[i] = sA[i];
    float m16[5], e15[5];
    #pragma unroll
    for (int i = 0; i < 5; i++) { m16[i] = sm16[i]; e15[i] = se15[i]; }

    // warm chunks (diagonal Tmid dynamics)
    float* pcs = g_cs + (unsigned)b;
    float tm[5];
    #pragma unroll
    for (int i = 0; i < 5; i++) tm[i] = fmaf(0.7f, gt0, 0.3f * ta0);
    float h47 = 0.f;
    #pragma unroll
    for (int j = 0; j < WCH; j++) {
        #pragma unroll
        for (int i = 0; i < 5; i++)
            pcs[(j * 6 + 1 + i) * B_LEN] = tm[i];
        if (j == WCH - 1) {
            h47 = e15[0] * tm[0];
            #pragma unroll
            for (int i = 1; i < 5; i++) h47 = fmaf(e15[i], tm[i], h47);
        }
        #pragma unroll
        for (int i = 0; i < 5; i++)
            tm[i] = fmaf(m16[i], tm[i], wd[j * 5 + i]);
    }
    float x[6];
    x[0] = tzz47 + h47;
    #pragma unroll
    for (int i = 0; i < 5; i++) x[1 + i] = tm[i];

    // 22 batches of 4 chunks (87 real + 1 pad; pad computed but never stored)
    pcs = g_cs + (unsigned)(WCH * 6 * B_LEN + b);
    #pragma unroll
    for (int batch = 0; batch < 22; batch++) {
        const int cu = batch & 1;
        if (batch < 21) {
            const float* pn = pd + (unsigned)(24 * B_LEN);
            #pragma unroll
            for (int q = 0; q < 24; q++) buf[cu ^ 1][q] = pn[q * B_LEN];
        }
        const int nc = (batch < 21) ? 4 : 3;
        #pragma unroll
        for (int c = 0; c < 4; c++) {
            const bool live = (c < nc);
            if (live) {
                #pragma unroll
                for (int k = 0; k < 6; k++) pcs[(c * 6 + k) * B_LEN] = x[k];
            }
            float y[6];
            #pragma unroll
            for (int i = 0; i < 6; i++) {
                float a = buf[cu][c * 6 + i];
                #pragma unroll
                for (int k = 0; k < 6; k++) a = fmaf(A[i * 6 + k], x[k], a);
                y[i] = a;
            }
            if (live) {
                #pragma unroll
                for (int k = 0; k < 6; k++) x[k] = y[k];
            }
        }
        pd  += (unsigned)(24 * B_LEN);
        pcs += (unsigned)(24 * B_LEN);
    }
}

// ---------------------------------------------------------------------------
// Emit: out[t] = tzz[t] + correction(chunk-start state). Vectorized:
// thread -> (4 consecutive b, 1 t); all gmem traffic 128-bit.
// ---------------------------------------------------------------------------
__global__ __launch_bounds__(256) void k_emit(float* __restrict__ out)
{
    __shared__ float sm[32][33];
    __shared__ float s_r0p[17 * 6];
    __shared__ float s_e[16 * 5];
    const int tid = threadIdx.x;
    if (tid < 102) s_r0p[tid] = g_r0p[tid];
    if (tid < 80)  s_e[tid]   = g_e[tid];
    __syncthreads();

    const int b0 = blockIdx.x * 32;
    const int t0 = blockIdx.y * 32;

    // compute phase: bq = tid&7 (b-quad), tt = tid>>3 (t within tile)
    {
        const int bq = tid & 7;
        const int tt = tid >> 3;
        const int t  = t0 + tt;
        const int jj = t >> 4;
        const int s  = t & 15;
        const bool warm = (jj < WCH);
        const int bb = 4 * bq;               // local b offset

        const float4* pcs = reinterpret_cast<const float4*>(
            g_cs + (unsigned)(jj * 6 * B_LEN + b0 + bb));
        float4 cs[6];
        #pragma unroll
        for (int k = 0; k < 6; k++) cs[k] = pcs[k * (B_LEN / 4)];

        float4 v = *reinterpret_cast<const float4*>(
            g_tzz + (unsigned)(t * B_LEN + b0 + bb));
        if (warm) {
            #pragma unroll
            for (int i = 0; i < 5; i++) {
                const float w = s_e[s * 5 + i];
                v.x = fmaf(w, cs[1 + i].x, v.x);
                v.y = fmaf(w, cs[1 + i].y, v.y);
                v.z = fmaf(w, cs[1 + i].z, v.z);
                v.w = fmaf(w, cs[1 + i].w, v.w);
            }
        } else {
            #pragma unroll
            for (int k = 0; k < 6; k++) {
                const float w = s_r0p[(s + 1) * 6 + k];
                v.x = fmaf(w, cs[k].x, v.x);
                v.y = fmaf(w, cs[k].y, v.y);
                v.z = fmaf(w, cs[k].z, v.z);
                v.w = fmaf(w, cs[k].w, v.w);
            }
        }
        sm[tt][bb + 0] = v.x;
        sm[tt][bb + 1] = v.y;
        sm[tt][bb + 2] = v.z;
        sm[tt][bb + 3] = v.w;
    }
    __syncthreads();

    // output phase: r2 = tid&31 (b-row), tq = tid>>5 (t-quad); STG.128 along t
    {
        const int r2 = tid & 31;
        const int tq = tid >> 5;
        float4 o;
        o.x = sm[4 * tq + 0][r2];
        o.y = sm[4 * tq + 1][r2];
        o.z = sm[4 * tq + 2][r2];
        o.w = sm[4 * tq + 3][r2];
        *reinterpret_cast<float4*>(
            out + (unsigned)((b0 + r2) * T_LEN + t0 + 4 * tq)) = o;
    }
}

extern "C" void kernel_launch(void* const* d_in, const int* in_sizes, int n_in,
                              void* d_out, int out_size) {
    const float* X          = (const float*)d_in[0];
    const float* rcR        = (const float*)d_in[1];
    const float* rcC        = (const float*)d_in[2];
    const float* winR       = (const float*)d_in[3];
    const float* hvac_gain  = (const float*)d_in[4];
    const float* W1         = (const float*)d_in[5];
    const float* B1         = (const float*)d_in[6];
    const float* W2         = (const float*)d_in[7];
    const float* B2         = (const float*)d_in[8];
    const float* int_gain   = (const float*)d_in[9];
    const float* direct_gain= (const float*)d_in[10];
    const float* abs_wall   = (const float*)d_in[11];
    const float* abs_roof   = (const float*)d_in[12];
    const float* zone_C_inv = (const float*)d_in[13];
    float* out = (float*)d_out;

    k_pre<<<1, 32>>>(rcR, rcC, winR, W1, B1, W2, B2,
                     int_gain, hvac_gain, direct_gain,
                     abs_wall, abs_roof, zone_C_inv);
    dim3 gA(B_LEN / 64, N_CH);
    kA<<<gA, 256>>>(X);
    k_scan<<<B_LEN / 64, 64>>>(X, rcR, rcC, winR, abs_wall, abs_roof,
                               zone_C_inv);
    dim3 ge(B_LEN / 32, T_LEN / 32);
    k_emit<<<ge, 256>>>(out);
}

// round 15
// speedup vs baseline: 1.0277x; 1.0277x over previous
#include <cuda_runtime.h>
#include <math.h>

#define T_LEN 1440
#define B_LEN 2048
#define N_RC  5
#define L_CH  16
#define N_CH  90      // 1440/16
#define WCH   3       // warm chunks (t < 48)

typedef unsigned long long u64;

__device__ float g_tzz[T_LEN * B_LEN];          // zero-state Tz trajectory
__device__ float g_d [(N_CH + 2) * 6 * B_LEN];  // per-chunk offsets (+pad)
__device__ float g_cs[N_CH * 6 * B_LEN];        // chunk-start states
__device__ float g_r0p[17 * 6];                 // row0(A^n), n=1..16 (from scan)
__device__ float g_e[16 * 5];                   // g*ri_i*m_i^s      (from scan)
__device__ u64   g_swab[64];                    // [2h]=w1a dup, [2h+1]=w1b dup
__device__ u64   g_sbw2[64];                    // [2h]=b1 dup,  [2h+1]=0.5*w2 dup
__device__ u64   g_cdup[3];                     // C0,C1,CB duplicated pairs
__device__ float g_c[27];                       // scalars + replay arrays

__device__ __forceinline__ float sp(float x) {
    if (x > 20.f)  return x;
    if (x < -20.f) return expf(x);
    return log1pf(expf(x));
}

__device__ __forceinline__ u64 pack2(float lo, float hi) {
    u64 r; asm("mov.b64 %0,{%1,%2};" : "=l"(r) : "f"(lo), "f"(hi)); return r;
}
__device__ __forceinline__ void unpack2(u64 v, float& lo, float& hi) {
    asm("mov.b64 {%0,%1},%2;" : "=f"(lo), "=f"(hi) : "l"(v));
}
__device__ __forceinline__ u64 fma2(u64 a, u64 b, u64 c) {
    u64 d; asm("fma.rn.f32x2 %0,%1,%2,%3;" : "=l"(d) : "l"(a), "l"(b), "l"(c)); return d;
}

struct P { float ri[N_RC], m[N_RC], kta[N_RC], ks[N_RC], alpha, g, gw; };

__device__ __forceinline__ void loadP(P& p,
    const float* rcR, const float* rcC, const float* winR,
    const float* paw, const float* par, const float* pcz)
{
    const float aw = 0.5f * sp(paw[0]);
    const float ar = 0.5f * sp(par[0]);
    float Rsum = 0.f;
    #pragma unroll
    for (int i = 0; i < N_RC; i++) {
        const float r = sp(rcR[i]) * 0.1f;
        const float c = sp(rcC[i]) * 1e-5f;
        const float a = (i < 4) ? aw : ar;
        p.ri[i] = r; Rsum += r;
        const float cd = c * 900.f;
        p.kta[i] = cd * r;
        p.m[i]   = 1.f - 2.f * cd * r;
        p.ks[i]  = cd * a;
    }
    const float win = (sp(winR[0]) + sp(winR[1])) * 0.5f;
    const float cz  = sp(pcz[0]) * 1e-5f;
    p.g     = cz * 900.f;
    p.alpha = 1.f - p.g * (Rsum + win);
    p.gw    = p.g * win;
}

__device__ __forceinline__ void hstep(const P& p, float x[6]) {
    float tz = x[0];
    float S = x[1] * p.ri[0];
    S = fmaf(x[2], p.ri[1], S);
    S = fmaf(x[3], p.ri[2], S);
    S = fmaf(x[4], p.ri[3], S);
    S = fmaf(x[5], p.ri[4], S);
    const float tznew = fmaf(p.alpha, tz, p.g * S);
    #pragma unroll
    for (int i = 0; i < N_RC; i++)
        x[1 + i] = fmaf(p.kta[i], tz, p.m[i] * x[1 + i]);
    x[0] = tznew;
}

// ---------------------------------------------------------------------------
// Precompute all scalar constants + packed weight tables. 1 block, 32 thr.
// ---------------------------------------------------------------------------
__global__ void k_pre(
    const float* __restrict__ rcR, const float* __restrict__ rcC,
    const float* __restrict__ winR,
    const float* __restrict__ W1, const float* __restrict__ B1,
    const float* __restrict__ W2, const float* __restrict__ B2,
    const float* __restrict__ pig, const float* __restrict__ phg,
    const float* __restrict__ pdg,
    const float* __restrict__ paw, const float* __restrict__ par,
    const float* __restrict__ pcz)
{
    const int tid = threadIdx.x;
    {
        const float wa = W1[2 * tid], wb = W1[2 * tid + 1];
        g_swab[2 * tid]     = pack2(wa, wa);
        g_swab[2 * tid + 1] = pack2(wb, wb);
        const float b1 = B1[tid], w2h = 0.5f * W2[tid];
        g_sbw2[2 * tid]     = pack2(b1, b1);
        g_sbw2[2 * tid + 1] = pack2(w2h, w2h);
    }
    if (tid == 0) {
        const float gi  = 0.1f * sp(pig[0]);
        const float gh  = 0.1f * sp(phg[0]);
        const float gd  = 0.5f * sp(pdg[0]);
        const float g   = sp(pcz[0]) * 1e-5f * 900.f;
        const float win = (sp(winR[0]) + sp(winR[1])) * 0.5f;
        const float aw  = 0.5f * sp(paw[0]);
        const float ar  = 0.5f * sp(par[0]);
        float Rsum = 0.f;
        #pragma unroll
        for (int i = 0; i < 5; i++) {
            const float r = sp(rcR[i]) * 0.1f;
            const float c = sp(rcC[i]) * 1e-5f;
            const float a = (i < 4) ? aw : ar;
            Rsum += r;
            const float cd = c * 900.f;
            g_c[7 + i]  = r;                   // ri
            g_c[12 + i] = 1.f - 2.f * cd * r;  // m
            g_c[17 + i] = cd * r;              // kta
            g_c[22 + i] = cd * a;              // ks
        }
        g_c[0] = g * win;      // gw
        g_c[1] = g * gd;       // gds
        g_c[2] = g * gh;       // ghs
        g_c[3] = g * gi;       // gis
        g_c[4] = g * gi;       // ggi
        g_c[5] = 1.f - g * (Rsum + win);  // alpha
        g_c[6] = g;
        float C0 = 0.f, C1 = 0.f, CB = B2[0];
        for (int h = 0; h < 32; h++) {
            const float w2h = 0.5f * W2[h];
            C0 = fmaf(w2h, W1[2 * h], C0);
            C1 = fmaf(w2h, W1[2 * h + 1], C1);
            CB = fmaf(w2h, B1[h], CB);
        }
        g_cdup[0] = pack2(C0, C0);
        g_cdup[1] = pack2(C1, C1);
        g_cdup[2] = pack2(CB, CB);
    }
}

// swizzled physical column for logical column L (compile-time at use sites)
#define SWC(L) ((((L) & ~3)) | (((((L) & 3)) + (((L) >> 5) & 3)) & 3))
#define SINR(L, R) s_in[SWC(L)][R]

// ---------------------------------------------------------------------------
// Phase A (fused drives + zero-state replay).
// 256 threads: staging (8 rows/thread) -> MLP (4 timesteps/thread, all
// threads) -> replay (threads 0..63, one chain per batch row).
// ---------------------------------------------------------------------------
__global__ __launch_bounds__(256) void kA(const float* __restrict__ X)
{
    __shared__ float s_in[112][65];          // [physical col][row]
    __shared__ float u_s[64][17];            // per-(row,step) drive term
    __shared__ __align__(16) u64 swab[64];
    __shared__ __align__(16) u64 sbw2[64];
    __shared__ float s_c[5];
    __shared__ u64 s_cd[3];
    const int tid = threadIdx.x;
    if (tid < 64) { swab[tid] = g_swab[tid]; sbw2[tid] = g_sbw2[tid]; }
    else if (tid < 69)  s_c[tid - 64]  = g_c[tid - 64];
    else if (tid < 72)  s_cd[tid - 69] = g_cdup[tid - 69];

    const int j  = blockIdx.y;
    const bool warm = (j < WCH);
    const int t0 = j * L_CH;
    const int b0 = blockIdx.x * 64;

    // stage 64 rows x 28 float4: 256 threads, 8 rows each, coalesced.
    {
        const int q  = tid & 31;
        const int rh = tid >> 5;             // 0..7
        if (q < 28) {
            const float4* src = reinterpret_cast<const float4*>(X)
                + (size_t)b0 * 2520 + (size_t)rh * 2520 + (size_t)j * 28 + q;
            const int qh = q >> 3;
            float* d0 = &s_in[4 * q + ((0 + qh) & 3)][rh];
            float* d1 = &s_in[4 * q + ((1 + qh) & 3)][rh];
            float* d2 = &s_in[4 * q + ((2 + qh) & 3)][rh];
            float* d3 = &s_in[4 * q + ((3 + qh) & 3)][rh];
            #pragma unroll
            for (int k = 0; k < 8; k++) {
                const float4 v = src[(size_t)k * 8 * 2520];  // rows rh+8k
                d0[8 * k] = v.x;
                d1[8 * k] = v.y;
                d2[8 * k] = v.z;
                d3[8 * k] = v.w;
            }
        }
    }
    __syncthreads();

    // MLP phase: thread -> (row = tid&63, timesteps 4*pg .. 4*pg+3)
    {
        const float gw  = s_c[0];
        const float gds = s_c[1];
        const float ghs = s_c[2];
        const float gis = s_c[3];
        const float ggi = s_c[4];
        const u64 c0d = s_cd[0], c1d = s_cd[1], cbd = s_cd[2];

        const int row = tid & 63;
        const int pg  = tid >> 6;            // 0..3
        u64 X0p[2], X1p[2], acc[2];
        float uu[4];
        #pragma unroll
        for (int pp = 0; pp < 2; pp++) {
            const int s0 = 4 * pg + 2 * pp, s1 = s0 + 1;
            const float ta0 = SINR(7 * s0 + 1, row), so0 = SINR(7 * s0 + 2, row);
            const float x00 = SINR(7 * s0 + 3, row), x10 = SINR(7 * s0 + 4, row);
            const float x20 = SINR(7 * s0 + 5, row), hv0 = SINR(7 * s0 + 6, row);
            const float ta1 = SINR(7 * s1 + 1, row), so1 = SINR(7 * s1 + 2, row);
            const float x01 = SINR(7 * s1 + 3, row), x11 = SINR(7 * s1 + 4, row);
            const float x21 = SINR(7 * s1 + 5, row), hv1 = SINR(7 * s1 + 6, row);
            X0p[pp] = pack2(x00, x01);
            X1p[pp] = pack2(x10, x11);
            acc[pp] = fma2(c0d, X0p[pp], fma2(c1d, X1p[pp], cbd));
            uu[2 * pp]     = fmaf(gw, ta0, fmaf(gds, so0, fmaf(ghs, hv0, gis * x20)));
            uu[2 * pp + 1] = fmaf(gw, ta1, fmaf(gds, so1, fmaf(ghs, hv1, gis * x21)));
        }
        #pragma unroll 8
        for (int h = 0; h < 32; h++) {
            const ulonglong2 wab = *reinterpret_cast<const ulonglong2*>(&swab[2 * h]);
            const ulonglong2 bw2 = *reinterpret_cast<const ulonglong2*>(&sbw2[2 * h]);
            #pragma unroll
            for (int pp = 0; pp < 2; pp++) {
                u64 z  = fma2(wab.x, X0p[pp], fma2(wab.y, X1p[pp], bw2.x));
                u64 za = z & 0x7FFFFFFF7FFFFFFFULL;      // |z| per half
                acc[pp] = fma2(bw2.y, za, acc[pp]);      // += 0.5*w2*|z|
            }
        }
        #pragma unroll
        for (int pp = 0; pp < 2; pp++) {
            float a0, a1; unpack2(acc[pp], a0, a1);
            const float sg0 = __fdividef(1.f, 1.f + __expf(-a0));
            const float sg1 = __fdividef(1.f, 1.f + __expf(-a1));
            uu[2 * pp]     = fmaf(ggi, sg0, uu[2 * pp]);
            uu[2 * pp + 1] = fmaf(ggi, sg1, uu[2 * pp + 1]);
        }
        #pragma unroll
        for (int k = 0; k < 4; k++) u_s[row][4 * pg + k] = uu[k];
    }
    __syncthreads();

    // Replay phase: threads 0..63, one sequential chain per batch row.
    if (tid < 64) {
        const float alpha = g_c[5];
        const float g     = g_c[6];
        float ri[5], m[5], kta[5], ks[5];
        #pragma unroll
        for (int i = 0; i < 5; i++) {
            ri[i]  = g_c[7 + i];
            m[i]   = g_c[12 + i];
            kta[i] = g_c[17 + i];
            ks[i]  = g_c[22 + i];
        }

        const int b = b0 + tid;
        float* pz = g_tzz + (unsigned)(t0 * B_LEN + b);   // + s*2048 (imm)
        float tm[5] = {0.f, 0.f, 0.f, 0.f, 0.f};
        float tz = 0.f;
        #pragma unroll
        for (int s = 0; s < 16; s++) {
            const float tac = SINR(7 * s + 1, tid);
            const float soc = SINR(7 * s + 2, tid);
            const float us  = u_s[tid][s];
            float tzc;
            if (warm) tzc = SINR(7 * s, tid);    // exogenous gt carry
            else      tzc = tz;
            float S = tm[0] * ri[0];
            S = fmaf(tm[1], ri[1], S);
            S = fmaf(tm[2], ri[2], S);
            S = fmaf(tm[3], ri[3], S);
            S = fmaf(tm[4], ri[4], S);
            const float tznew = fmaf(alpha, tzc, fmaf(g, S, us));
            pz[s * B_LEN] = tznew;
            const float tpz = tac + tzc;
            #pragma unroll
            for (int i = 0; i < 5; i++)
                tm[i] = fmaf(kta[i], tpz, fmaf(ks[i], soc, m[i] * tm[i]));
            tz = tznew;
        }
        float* pd = g_d + (unsigned)(j * 6 * B_LEN + b);  // + i*2048 (imm)
        if (!warm) pd[0] = tz;
        #pragma unroll
        for (int i = 0; i < 5; i++) pd[(1 + i) * B_LEN] = tm[i];
    }
}

// ---------------------------------------------------------------------------
// Scan over chunks, 4-chunk double-buffered prefetch. Also emits the A-power
// tables to global (block 0) for k_emit.
// ---------------------------------------------------------------------------
__global__ __launch_bounds__(64) void k_scan(
    const float* __restrict__ X,
    const float* __restrict__ rcR, const float* __restrict__ rcC,
    const float* __restrict__ winR,
    const float* __restrict__ paw, const float* __restrict__ par,
    const float* __restrict__ pcz)
{
    __shared__ float sA[36];
    __shared__ float sm16[5], se15[5];
    const int tid = threadIdx.x;
    if (tid < 7) {
        P p; loadP(p, rcR, rcC, winR, paw, par, pcz);
        if (tid < 6) {
            float x[6] = {0.f, 0.f, 0.f, 0.f, 0.f, 0.f};
            x[tid] = 1.f;
            for (int n = 1; n <= L_CH; n++) {
                hstep(p, x);
                if (blockIdx.x == 0) g_r0p[n * 6 + tid] = x[0];
            }
            #pragma unroll
            for (int i = 0; i < 6; i++) sA[i * 6 + tid] = x[i];
        } else {
            float mp[5] = {1.f, 1.f, 1.f, 1.f, 1.f};
            for (int s = 0; s < L_CH; s++) {
                #pragma unroll
                for (int i = 0; i < 5; i++) {
                    const float e = p.g * p.ri[i] * mp[i];
                    if (blockIdx.x == 0) g_e[s * 5 + i] = e;
                    if (s == 15) se15[i] = e;
                    mp[i] *= p.m[i];
                }
            }
            #pragma unroll
            for (int i = 0; i < 5; i++) sm16[i] = mp[i];
        }
    }

    const int b = blockIdx.x * 64 + tid;

    // prefetch warm d's and initial values
    const float* pdw = g_d + (unsigned)b;
    float wd[15];
    #pragma unroll
    for (int j = 0; j < WCH; j++)
        #pragma unroll
        for (int i = 0; i < 5; i++)
            wd[j * 5 + i] = pdw[(j * 6 + 1 + i) * B_LEN];
    const float gt0   = X[(size_t)b * (T_LEN * 7)];
    const float ta0   = X[(size_t)b * (T_LEN * 7) + 1];
    const float tzz47 = g_tzz[(unsigned)(47 * B_LEN + b)];

    // preload batch 0 (chunks 3..6)
    float buf[2][24];
    const float* pd = g_d + (unsigned)(WCH * 6 * B_LEN + b);
    #pragma unroll
    for (int q = 0; q < 24; q++) buf[0][q] = pd[q * B_LEN];

    __syncthreads();
    float A[36];
    #pragma unroll
    for (int i = 0; i < 36; i++) A[i] = sA[i];
    float m16[5], e15[5];
    #pragma unroll
    for (int i = 0; i < 5; i++) { m16[i] = sm16[i]; e15[i] = se15[i]; }

    // warm chunks (diagonal Tmid dynamics)
    float* pcs = g_cs + (unsigned)b;
    float tm[5];
    #pragma unroll
    for (int i = 0; i < 5; i++) tm[i] = fmaf(0.7f, gt0, 0.3f * ta0);
    float h47 = 0.f;
    #pragma unroll
    for (int j = 0; j < WCH; j++) {
        #pragma unroll
        for (int i = 0; i < 5; i++)
            pcs[(j * 6 + 1 + i) * B_LEN] = tm[i];
        if (j == WCH - 1) {
            h47 = e15[0] * tm[0];
            #pragma unroll
            for (int i = 1; i < 5; i++) h47 = fmaf(e15[i], tm[i], h47);
        }
        #pragma unroll
        for (int i = 0; i < 5; i++)
            tm[i] = fmaf(m16[i], tm[i], wd[j * 5 + i]);
    }
    float x[6];
    x[0] = tzz47 + h47;
    #pragma unroll
    for (int i = 0; i < 5; i++) x[1 + i] = tm[i];

    // 22 batches of 4 chunks (87 real + 1 pad; pad computed but never stored)
    pcs = g_cs + (unsigned)(WCH * 6 * B_LEN + b);
    #pragma unroll
    for (int batch = 0; batch < 22; batch++) {
        const int cu = batch & 1;
        if (batch < 21) {
            const float* pn = pd + (unsigned)(24 * B_LEN);
            #pragma unroll
            for (int q = 0; q < 24; q++) buf[cu ^ 1][q] = pn[q * B_LEN];
        }
        const int nc = (batch < 21) ? 4 : 3;
        #pragma unroll
        for (int c = 0; c < 4; c++) {
            const bool live = (c < nc);
            if (live) {
                #pragma unroll
                for (int k = 0; k < 6; k++) pcs[(c * 6 + k) * B_LEN] = x[k];
            }
            float y[6];
            #pragma unroll
            for (int i = 0; i < 6; i++) {
                float a = buf[cu][c * 6 + i];
                #pragma unroll
                for (int k = 0; k < 6; k++) a = fmaf(A[i * 6 + k], x[k], a);
                y[i] = a;
            }
            if (live) {
                #pragma unroll
                for (int k = 0; k < 6; k++) x[k] = y[k];
            }
        }
        pd  += (unsigned)(24 * B_LEN);
        pcs += (unsigned)(24 * B_LEN);
    }
}

// ---------------------------------------------------------------------------
// Emit: out[t] = tzz[t] + correction(chunk-start state).
// cs staged in smem once per block; tzz via LDG.128; output via fully
// coalesced STG.128 (warp = 4 rows x 8 float4 along t).
// ---------------------------------------------------------------------------
__global__ __launch_bounds__(256) void k_emit(float* __restrict__ out)
{
    __shared__ float sm[32][33];
    __shared__ float s_r0p[17 * 6];
    __shared__ float s_e[16 * 5];
    __shared__ __align__(16) float s_cs[12][32];   // 2 chunks x 6 comps x 32 b
    const int tid = threadIdx.x;
    const int b0 = blockIdx.x * 32;
    const int t0 = blockIdx.y * 32;
    const int jj0 = t0 >> 4;                        // first chunk of tile

    if (tid < 102) s_r0p[tid] = g_r0p[tid];
    if (tid >= 128 && tid < 208) s_e[tid - 128] = g_e[tid - 128];
    // cs staging: rows jj0*6 .. jj0*6+11 of g_cs, 32 b's each (coalesced)
    {
        const float* src = g_cs + (unsigned)(jj0 * 6 * B_LEN + b0);
        #pragma unroll
        for (int e = tid; e < 384; e += 256) {
            const int k  = e >> 5;
            const int bb = e & 31;
            s_cs[k][bb] = src[k * B_LEN + bb];
        }
    }
    __syncthreads();

    // compute phase: bq = tid&7 (b-quad), tt = tid>>3 (t within tile)
    {
        const int bq = tid & 7;
        const int tt = tid >> 3;
        const int t  = t0 + tt;
        const int ch = tt >> 4;              // chunk within tile (0/1)
        const int s  = t & 15;
        const bool warm = (jj0 + ch < WCH);
        const int bb = 4 * bq;

        float4 cs[6];
        #pragma unroll
        for (int k = 0; k < 6; k++)
            cs[k] = *reinterpret_cast<const float4*>(&s_cs[ch * 6 + k][bb]);

        float4 v = *reinterpret_cast<const float4*>(
            g_tzz + (unsigned)(t * B_LEN + b0 + bb));
        if (warm) {
            #pragma unroll
            for (int i = 0; i < 5; i++) {
                const float w = s_e[s * 5 + i];
                v.x = fmaf(w, cs[1 + i].x, v.x);
                v.y = fmaf(w, cs[1 + i].y, v.y);
                v.z = fmaf(w, cs[1 + i].z, v.z);
                v.w = fmaf(w, cs[1 + i].w, v.w);
            }
        } else {
            #pragma unroll
            for (int k = 0; k < 6; k++) {
                const float w = s_r0p[(s + 1) * 6 + k];
                v.x = fmaf(w, cs[k].x, v.x);
                v.y = fmaf(w, cs[k].y, v.y);
                v.z = fmaf(w, cs[k].z, v.z);
                v.w = fmaf(w, cs[k].w, v.w);
            }
        }
        sm[tt][bb + 0] = v.x;
        sm[tt][bb + 1] = v.y;
        sm[tt][bb + 2] = v.z;
        sm[tt][bb + 3] = v.w;
    }
    __syncthreads();

    // output: warp w -> rows 4w..4w+3; lane l -> row 4w+(l>>3), t-quad l&7.
    // Each STG.128 warp-instruction writes 4 rows x 128 contiguous bytes.
    {
        const int w = tid >> 5;
        const int l = tid & 31;
        const int r  = 4 * w + (l >> 3);
        const int tq = l & 7;
        float4 o;
        o.x = sm[4 * tq + 0][r];
        o.y = sm[4 * tq + 1][r];
        o.z = sm[4 * tq + 2][r];
        o.w = sm[4 * tq + 3][r];
        *reinterpret_cast<float4*>(
            out + (unsigned)((b0 + r) * T_LEN + t0 + 4 * tq)) = o;
    }
}

extern "C" void kernel_launch(void* const* d_in, const int* in_sizes, int n_in,
                              void* d_out, int out_size) {
    const float* X          = (const float*)d_in[0];
    const float* rcR        = (const float*)d_in[1];
    const float* rcC        = (const float*)d_in[2];
    const float* winR       = (const float*)d_in[3];
    const float* hvac_gain  = (const float*)d_in[4];
    const float* W1         = (const float*)d_in[5];
    const float* B1         = (const float*)d_in[6];
    const float* W2         = (const float*)d_in[7];
    const float* B2         = (const float*)d_in[8];
    const float* int_gain   = (const float*)d_in[9];
    const float* direct_gain= (const float*)d_in[10];
    const float* abs_wall   = (const float*)d_in[11];
    const float* abs_roof   = (const float*)d_in[12];
    const float* zone_C_inv = (const float*)d_in[13];
    float* out = (float*)d_out;

    k_pre<<<1, 32>>>(rcR, rcC, winR, W1, B1, W2, B2,
                     int_gain, hvac_gain, direct_gain,
                     abs_wall, abs_roof, zone_C_inv);
    dim3 gA(B_LEN / 64, N_CH);
    kA<<<gA, 256>>>(X);
    k_scan<<<B_LEN / 64, 64>>>(X, rcR, rcC, winR, abs_wall, abs_roof,
                               zone_C_inv);
    dim3 ge(B_LEN / 32, T_LEN / 32);
    k_emit<<<ge, 256>>>(out);
}

// round 16
// speedup vs baseline: 1.0548x; 1.0264x over previous
#include <cuda_runtime.h>
#include <math.h>

#define T_LEN 1440
#define B_LEN 2048
#define N_RC  5
#define L_CH  16
#define N_CH  90      // 1440/16
#define WCH   3       // warm chunks (t < 48)

typedef unsigned long long u64;

__device__ float g_tzz[T_LEN * B_LEN];          // zero-state Tz trajectory
__device__ float g_d [(N_CH + 2) * 6 * B_LEN];  // per-chunk offsets (+pad)
__device__ float g_cs[N_CH * 6 * B_LEN];        // chunk-start states
__device__ float g_r0p[17 * 6];                 // row0(A^n), n=1..16 (from scan)
__device__ float g_e[16 * 5];                   // g*ri_i*m_i^s      (from scan)
__device__ u64   g_swab[64];                    // [2h]=w1a dup, [2h+1]=w1b dup
__device__ u64   g_sbw2[64];                    // [2h]=b1 dup,  [2h+1]=0.5*w2 dup
__device__ u64   g_cdup[3];                     // C0,C1,CB duplicated pairs
__device__ float g_c[27];                       // scalars + replay arrays

__device__ __forceinline__ float sp(float x) {
    if (x > 20.f)  return x;
    if (x < -20.f) return expf(x);
    return log1pf(expf(x));
}

__device__ __forceinline__ u64 pack2(float lo, float hi) {
    u64 r; asm("mov.b64 %0,{%1,%2};" : "=l"(r) : "f"(lo), "f"(hi)); return r;
}
__device__ __forceinline__ void unpack2(u64 v, float& lo, float& hi) {
    asm("mov.b64 {%0,%1},%2;" : "=f"(lo), "=f"(hi) : "l"(v));
}
__device__ __forceinline__ u64 fma2(u64 a, u64 b, u64 c) {
    u64 d; asm("fma.rn.f32x2 %0,%1,%2,%3;" : "=l"(d) : "l"(a), "l"(b), "l"(c)); return d;
}

struct P { float ri[N_RC], m[N_RC], kta[N_RC], ks[N_RC], alpha, g, gw; };

__device__ __forceinline__ void loadP(P& p,
    const float* rcR, const float* rcC, const float* winR,
    const float* paw, const float* par, const float* pcz)
{
    const float aw = 0.5f * sp(paw[0]);
    const float ar = 0.5f * sp(par[0]);
    float Rsum = 0.f;
    #pragma unroll
    for (int i = 0; i < N_RC; i++) {
        const float r = sp(rcR[i]) * 0.1f;
        const float c = sp(rcC[i]) * 1e-5f;
        const float a = (i < 4) ? aw : ar;
        p.ri[i] = r; Rsum += r;
        const float cd = c * 900.f;
        p.kta[i] = cd * r;
        p.m[i]   = 1.f - 2.f * cd * r;
        p.ks[i]  = cd * a;
    }
    const float win = (sp(winR[0]) + sp(winR[1])) * 0.5f;
    const float cz  = sp(pcz[0]) * 1e-5f;
    p.g     = cz * 900.f;
    p.alpha = 1.f - p.g * (Rsum + win);
    p.gw    = p.g * win;
}

__device__ __forceinline__ void hstep(const P& p, float x[6]) {
    float tz = x[0];
    float S = x[1] * p.ri[0];
    S = fmaf(x[2], p.ri[1], S);
    S = fmaf(x[3], p.ri[2], S);
    S = fmaf(x[4], p.ri[3], S);
    S = fmaf(x[5], p.ri[4], S);
    const float tznew = fmaf(p.alpha, tz, p.g * S);
    #pragma unroll
    for (int i = 0; i < N_RC; i++)
        x[1 + i] = fmaf(p.kta[i], tz, p.m[i] * x[1 + i]);
    x[0] = tznew;
}

// ---------------------------------------------------------------------------
// Precompute all scalar constants + packed weight tables. 1 block, 32 thr.
// ---------------------------------------------------------------------------
__global__ void k_pre(
    const float* __restrict__ rcR, const float* __restrict__ rcC,
    const float* __restrict__ winR,
    const float* __restrict__ W1, const float* __restrict__ B1,
    const float* __restrict__ W2, const float* __restrict__ B2,
    const float* __restrict__ pig, const float* __restrict__ phg,
    const float* __restrict__ pdg,
    const float* __restrict__ paw, const float* __restrict__ par,
    const float* __restrict__ pcz)
{
    const int tid = threadIdx.x;
    {
        const float wa = W1[2 * tid], wb = W1[2 * tid + 1];
        g_swab[2 * tid]     = pack2(wa, wa);
        g_swab[2 * tid + 1] = pack2(wb, wb);
        const float b1 = B1[tid], w2h = 0.5f * W2[tid];
        g_sbw2[2 * tid]     = pack2(b1, b1);
        g_sbw2[2 * tid + 1] = pack2(w2h, w2h);
    }
    if (tid == 0) {
        const float gi  = 0.1f * sp(pig[0]);
        const float gh  = 0.1f * sp(phg[0]);
        const float gd  = 0.5f * sp(pdg[0]);
        const float g   = sp(pcz[0]) * 1e-5f * 900.f;
        const float win = (sp(winR[0]) + sp(winR[1])) * 0.5f;
        const float aw  = 0.5f * sp(paw[0]);
        const float ar  = 0.5f * sp(par[0]);
        float Rsum = 0.f;
        #pragma unroll
        for (int i = 0; i < 5; i++) {
            const float r = sp(rcR[i]) * 0.1f;
            const float c = sp(rcC[i]) * 1e-5f;
            const float a = (i < 4) ? aw : ar;
            Rsum += r;
            const float cd = c * 900.f;
            g_c[7 + i]  = r;                   // ri
            g_c[12 + i] = 1.f - 2.f * cd * r;  // m
            g_c[17 + i] = cd * r;              // kta
            g_c[22 + i] = cd * a;              // ks
        }
        g_c[0] = g * win;      // gw
        g_c[1] = g * gd;       // gds
        g_c[2] = g * gh;       // ghs
        g_c[3] = g * gi;       // gis
        g_c[4] = g * gi;       // ggi
        g_c[5] = 1.f - g * (Rsum + win);  // alpha
        g_c[6] = g;
        float C0 = 0.f, C1 = 0.f, CB = B2[0];
        for (int h = 0; h < 32; h++) {
            const float w2h = 0.5f * W2[h];
            C0 = fmaf(w2h, W1[2 * h], C0);
            C1 = fmaf(w2h, W1[2 * h + 1], C1);
            CB = fmaf(w2h, B1[h], CB);
        }
        g_cdup[0] = pack2(C0, C0);
        g_cdup[1] = pack2(C1, C1);
        g_cdup[2] = pack2(CB, CB);
    }
}

// swizzled physical column for logical column L (compile-time at use sites)
#define SWC(L) ((((L) & ~3)) | (((((L) & 3)) + (((L) >> 5) & 3)) & 3))
#define SINR(L, R) s_in[SWC(L)][R]

// ---------------------------------------------------------------------------
// Phase A (fused drives + zero-state replay).
// 256 threads: staging -> MLP (u stored in-place into s_in col 7s+5) ->
// replay (threads 0..63). smem ~30KB -> 7 blocks/SM.
// ---------------------------------------------------------------------------
__global__ __launch_bounds__(256) void kA(const float* __restrict__ X)
{
    __shared__ float s_in[112][65];          // [physical col][row]
    __shared__ __align__(16) u64 swab[64];
    __shared__ __align__(16) u64 sbw2[64];
    __shared__ float s_c[5];
    __shared__ u64 s_cd[3];
    const int tid = threadIdx.x;
    if (tid < 64) { swab[tid] = g_swab[tid]; sbw2[tid] = g_sbw2[tid]; }
    else if (tid < 69)  s_c[tid - 64]  = g_c[tid - 64];
    else if (tid < 72)  s_cd[tid - 69] = g_cdup[tid - 69];

    const int j  = blockIdx.y;
    const bool warm = (j < WCH);
    const int t0 = j * L_CH;
    const int b0 = blockIdx.x * 64;

    // stage 64 rows x 28 float4: 256 threads, 8 rows each, coalesced.
    {
        const int q  = tid & 31;
        const int rh = tid >> 5;             // 0..7
        if (q < 28) {
            const float4* src = reinterpret_cast<const float4*>(X)
                + (size_t)b0 * 2520 + (size_t)rh * 2520 + (size_t)j * 28 + q;
            const int qh = q >> 3;
            float* d0 = &s_in[4 * q + ((0 + qh) & 3)][rh];
            float* d1 = &s_in[4 * q + ((1 + qh) & 3)][rh];
            float* d2 = &s_in[4 * q + ((2 + qh) & 3)][rh];
            float* d3 = &s_in[4 * q + ((3 + qh) & 3)][rh];
            #pragma unroll
            for (int k = 0; k < 8; k++) {
                const float4 v = src[(size_t)k * 8 * 2520];  // rows rh+8k
                d0[8 * k] = v.x;
                d1[8 * k] = v.y;
                d2[8 * k] = v.z;
                d3[8 * k] = v.w;
            }
        }
    }
    __syncthreads();

    // MLP phase: thread -> (row = tid&63, timesteps 4*pg .. 4*pg+3).
    // Result u[s] written in place to s_in col 7s+5 (x2 slot, dead after read).
    {
        const float gw  = s_c[0];
        const float gds = s_c[1];
        const float ghs = s_c[2];
        const float gis = s_c[3];
        const float ggi = s_c[4];
        const u64 c0d = s_cd[0], c1d = s_cd[1], cbd = s_cd[2];

        const int row = tid & 63;
        const int pg  = tid >> 6;            // 0..3
        u64 X0p[2], X1p[2], acc[2];
        float uu[4];
        #pragma unroll
        for (int pp = 0; pp < 2; pp++) {
            const int s0 = 4 * pg + 2 * pp, s1 = s0 + 1;
            const float ta0 = SINR(7 * s0 + 1, row), so0 = SINR(7 * s0 + 2, row);
            const float x00 = SINR(7 * s0 + 3, row), x10 = SINR(7 * s0 + 4, row);
            const float x20 = SINR(7 * s0 + 5, row), hv0 = SINR(7 * s0 + 6, row);
            const float ta1 = SINR(7 * s1 + 1, row), so1 = SINR(7 * s1 + 2, row);
            const float x01 = SINR(7 * s1 + 3, row), x11 = SINR(7 * s1 + 4, row);
            const float x21 = SINR(7 * s1 + 5, row), hv1 = SINR(7 * s1 + 6, row);
            X0p[pp] = pack2(x00, x01);
            X1p[pp] = pack2(x10, x11);
            acc[pp] = fma2(c0d, X0p[pp], fma2(c1d, X1p[pp], cbd));
            uu[2 * pp]     = fmaf(gw, ta0, fmaf(gds, so0, fmaf(ghs, hv0, gis * x20)));
            uu[2 * pp + 1] = fmaf(gw, ta1, fmaf(gds, so1, fmaf(ghs, hv1, gis * x21)));
        }
        #pragma unroll 8
        for (int h = 0; h < 32; h++) {
            const ulonglong2 wab = *reinterpret_cast<const ulonglong2*>(&swab[2 * h]);
            const ulonglong2 bw2 = *reinterpret_cast<const ulonglong2*>(&sbw2[2 * h]);
            #pragma unroll
            for (int pp = 0; pp < 2; pp++) {
                u64 z  = fma2(wab.x, X0p[pp], fma2(wab.y, X1p[pp], bw2.x));
                u64 za = z & 0x7FFFFFFF7FFFFFFFULL;      // |z| per half
                acc[pp] = fma2(bw2.y, za, acc[pp]);      // += 0.5*w2*|z|
            }
        }
        #pragma unroll
        for (int pp = 0; pp < 2; pp++) {
            float a0, a1; unpack2(acc[pp], a0, a1);
            const float sg0 = __fdividef(1.f, 1.f + __expf(-a0));
            const float sg1 = __fdividef(1.f, 1.f + __expf(-a1));
            uu[2 * pp]     = fmaf(ggi, sg0, uu[2 * pp]);
            uu[2 * pp + 1] = fmaf(ggi, sg1, uu[2 * pp + 1]);
        }
        #pragma unroll
        for (int k = 0; k < 4; k++)
            SINR(7 * (4 * pg + k) + 5, row) = uu[k];
    }
    __syncthreads();

    // Replay phase: threads 0..63, one sequential chain per batch row.
    if (tid < 64) {
        const float alpha = g_c[5];
        const float g     = g_c[6];
        float ri[5], m[5], kta[5], ks[5];
        #pragma unroll
        for (int i = 0; i < 5; i++) {
            ri[i]  = g_c[7 + i];
            m[i]   = g_c[12 + i];
            kta[i] = g_c[17 + i];
            ks[i]  = g_c[22 + i];
        }

        const int b = b0 + tid;
        float* pz = g_tzz + (unsigned)(t0 * B_LEN + b);   // + s*2048 (imm)
        float tm[5] = {0.f, 0.f, 0.f, 0.f, 0.f};
        float tz = 0.f;
        #pragma unroll
        for (int s = 0; s < 16; s++) {
            const float tac = SINR(7 * s + 1, tid);
            const float soc = SINR(7 * s + 2, tid);
            const float us  = SINR(7 * s + 5, tid);   // in-place u
            float tzc;
            if (warm) tzc = SINR(7 * s, tid);    // exogenous gt carry
            else      tzc = tz;
            float S = tm[0] * ri[0];
            S = fmaf(tm[1], ri[1], S);
            S = fmaf(tm[2], ri[2], S);
            S = fmaf(tm[3], ri[3], S);
            S = fmaf(tm[4], ri[4], S);
            const float tznew = fmaf(alpha, tzc, fmaf(g, S, us));
            pz[s * B_LEN] = tznew;
            const float tpz = tac + tzc;
            #pragma unroll
            for (int i = 0; i < 5; i++)
                tm[i] = fmaf(kta[i], tpz, fmaf(ks[i], soc, m[i] * tm[i]));
            tz = tznew;
        }
        float* pd = g_d + (unsigned)(j * 6 * B_LEN + b);  // + i*2048 (imm)
        if (!warm) pd[0] = tz;
        #pragma unroll
        for (int i = 0; i < 5; i++) pd[(1 + i) * B_LEN] = tm[i];
    }
}

// ---------------------------------------------------------------------------
// Scan over chunks, 4-chunk double-buffered prefetch. Also emits the A-power
// tables to global (block 0) for k_emit.
// ---------------------------------------------------------------------------
__global__ __launch_bounds__(64) void k_scan(
    const float* __restrict__ X,
    const float* __restrict__ rcR, const float* __restrict__ rcC,
    const float* __restrict__ winR,
    const float* __restrict__ paw, const float* __restrict__ par,
    const float* __restrict__ pcz)
{
    __shared__ float sA[36];
    __shared__ float sm16[5], se15[5];
    const int tid = threadIdx.x;
    if (tid < 7) {
        P p; loadP(p, rcR, rcC, winR, paw, par, pcz);
        if (tid < 6) {
            float x[6] = {0.f, 0.f, 0.f, 0.f, 0.f, 0.f};
            x[tid] = 1.f;
            for (int n = 1; n <= L_CH; n++) {
                hstep(p, x);
                if (blockIdx.x == 0) g_r0p[n * 6 + tid] = x[0];
            }
            #pragma unroll
            for (int i = 0; i < 6; i++) sA[i * 6 + tid] = x[i];
        } else {
            float mp[5] = {1.f, 1.f, 1.f, 1.f, 1.f};
            for (int s = 0; s < L_CH; s++) {
                #pragma unroll
                for (int i = 0; i < 5; i++) {
                    const float e = p.g * p.ri[i] * mp[i];
                    if (blockIdx.x == 0) g_e[s * 5 + i] = e;
                    if (s == 15) se15[i] = e;
                    mp[i] *= p.m[i];
                }
            }
            #pragma unroll
            for (int i = 0; i < 5; i++) sm16[i] = mp[i];
        }
    }

    const int b = blockIdx.x * 64 + tid;

    // prefetch warm d's and initial values
    const float* pdw = g_d + (unsigned)b;
    float wd[15];
    #pragma unroll
    for (int j = 0; j < WCH; j++)
        #pragma unroll
        for (int i = 0; i < 5; i++)
            wd[j * 5 + i] = pdw[(j * 6 + 1 + i) * B_LEN];
    const float gt0   = X[(size_t)b * (T_LEN * 7)];
    const float ta0   = X[(size_t)b * (T_LEN * 7) + 1];
    const float tzz47 = g_tzz[(unsigned)(47 * B_LEN + b)];

    // preload batch 0 (chunks 3..6)
    float buf[2][24];
    const float* pd = g_d + (unsigned)(WCH * 6 * B_LEN + b);
    #pragma unroll
    for (int q = 0; q < 24; q++) buf[0][q] = pd[q * B_LEN];

    __syncthreads();
    float A[36];
    #pragma unroll
    for (int i = 0; i < 36; i++) A[i] = sA[i];
    float m16[5], e15[5];
    #pragma unroll
    for (int i = 0; i < 5; i++) { m16[i] = sm16[i]; e15[i] = se15[i]; }

    // warm chunks (diagonal Tmid dynamics)
    float* pcs = g_cs + (unsigned)b;
    float tm[5];
    #pragma unroll
    for (int i = 0; i < 5; i++) tm[i] = fmaf(0.7f, gt0, 0.3f * ta0);
    float h47 = 0.f;
    #pragma unroll
    for (int j = 0; j < WCH; j++) {
        #pragma unroll
        for (int i = 0; i < 5; i++)
            pcs[(j * 6 + 1 + i) * B_LEN] = tm[i];
        if (j == WCH - 1) {
            h47 = e15[0] * tm[0];
            #pragma unroll
            for (int i = 1; i < 5; i++) h47 = fmaf(e15[i], tm[i], h47);
        }
        #pragma unroll
        for (int i = 0; i < 5; i++)
            tm[i] = fmaf(m16[i], tm[i], wd[j * 5 + i]);
    }
    float x[6];
    x[0] = tzz47 + h47;
    #pragma unroll
    for (int i = 0; i < 5; i++) x[1 + i] = tm[i];

    // 22 batches of 4 chunks (87 real + 1 pad; pad computed but never stored)
    pcs = g_cs + (unsigned)(WCH * 6 * B_LEN + b);
    #pragma unroll
    for (int batch = 0; batch < 22; batch++) {
        const int cu = batch & 1;
        if (batch < 21) {
            const float* pn = pd + (unsigned)(24 * B_LEN);
            #pragma unroll
            for (int q = 0; q < 24; q++) buf[cu ^ 1][q] = pn[q * B_LEN];
        }
        const int nc = (batch < 21) ? 4 : 3;
        #pragma unroll
        for (int c = 0; c < 4; c++) {
            const bool live = (c < nc);
            if (live) {
                #pragma unroll
                for (int k = 0; k < 6; k++) pcs[(c * 6 + k) * B_LEN] = x[k];
            }
            float y[6];
            #pragma unroll
            for (int i = 0; i < 6; i++) {
                float a = buf[cu][c * 6 + i];
                #pragma unroll
                for (int k = 0; k < 6; k++) a = fmaf(A[i * 6 + k], x[k], a);
                y[i] = a;
            }
            if (live) {
                #pragma unroll
                for (int k = 0; k < 6; k++) x[k] = y[k];
            }
        }
        pd  += (unsigned)(24 * B_LEN);
        pcs += (unsigned)(24 * B_LEN);
    }
}

// ---------------------------------------------------------------------------
// Emit: out[t] = tzz[t] + correction(chunk-start state).
// 64b x 48t tiles (3 chunks), cs staged in smem, LDG.128 tzz, coalesced
// STG.128 output.
// ---------------------------------------------------------------------------
__global__ __launch_bounds__(256) void k_emit(float* __restrict__ out)
{
    __shared__ float sm[48][65];
    __shared__ float s_r0p[17 * 6];
    __shared__ float s_e[16 * 5];
    __shared__ __align__(16) float s_cs[18][64];   // 3 chunks x 6 comps x 64 b
    const int tid = threadIdx.x;
    const int b0 = blockIdx.x * 64;
    const int t0 = blockIdx.y * 48;
    const int jj0 = blockIdx.y * 3;                 // first chunk of tile

    if (tid < 102) s_r0p[tid] = g_r0p[tid];
    if (tid >= 128 && tid < 208) s_e[tid - 128] = g_e[tid - 128];
    // cs staging: rows jj0*6 .. jj0*6+17 of g_cs, 64 b's each (coalesced)
    {
        const float* src = g_cs + (unsigned)(jj0 * 6 * B_LEN + b0);
        #pragma unroll
        for (int e = tid; e < 18 * 64; e += 256) {
            const int k  = e >> 6;
            const int bb = e & 63;
            s_cs[k][bb] = src[k * B_LEN + bb];
        }
    }
    __syncthreads();

    // compute phase: 3 iterations, one chunk each.
    // thread -> bb = 4*(tid&15), s = tid>>4 (t within chunk)
    {
        const int s  = tid >> 4;
        const int bb = 4 * (tid & 15);
        #pragma unroll
        for (int it = 0; it < 3; it++) {
            const int tt = it * 16 + s;
            const int t  = t0 + tt;
            const bool warm = (jj0 + it < WCH);

            float4 cs[6];
            #pragma unroll
            for (int k = 0; k < 6; k++)
                cs[k] = *reinterpret_cast<const float4*>(&s_cs[it * 6 + k][bb]);

            float4 v = *reinterpret_cast<const float4*>(
                g_tzz + (unsigned)(t * B_LEN + b0 + bb));
            if (warm) {
                #pragma unroll
                for (int i = 0; i < 5; i++) {
                    const float w = s_e[s * 5 + i];
                    v.x = fmaf(w, cs[1 + i].x, v.x);
                    v.y = fmaf(w, cs[1 + i].y, v.y);
                    v.z = fmaf(w, cs[1 + i].z, v.z);
                    v.w = fmaf(w, cs[1 + i].w, v.w);
                }
            } else {
                #pragma unroll
                for (int k = 0; k < 6; k++) {
                    const float w = s_r0p[(s + 1) * 6 + k];
                    v.x = fmaf(w, cs[k].x, v.x);
                    v.y = fmaf(w, cs[k].y, v.y);
                    v.z = fmaf(w, cs[k].z, v.z);
                    v.w = fmaf(w, cs[k].w, v.w);
                }
            }
            sm[tt][bb + 0] = v.x;
            sm[tt][bb + 1] = v.y;
            sm[tt][bb + 2] = v.z;
            sm[tt][bb + 3] = v.w;
        }
    }
    __syncthreads();

    // output: warp w -> rows 8w..8w+7; lane l -> row 8w+(l>>2), t-quads.
    // 3 iterations cover 12 float4 per row. Fully coalesced STG.128.
    {
        const int w = tid >> 5;
        const int l = tid & 31;
        const int r = 8 * w + (l >> 2);
        #pragma unroll
        for (int it = 0; it < 3; it++) {
            const int tq = it * 4 + (l & 3);
            float4 o;
            o.x = sm[4 * tq + 0][r];
            o.y = sm[4 * tq + 1][r];
            o.z = sm[4 * tq + 2][r];
            o.w = sm[4 * tq + 3][r];
            *reinterpret_cast<float4*>(
                out + (unsigned)((b0 + r) * T_LEN + t0 + 4 * tq)) = o;
        }
    }
}

extern "C" void kernel_launch(void* const* d_in, const int* in_sizes, int n_in,
                              void* d_out, int out_size) {
    const float* X          = (const float*)d_in[0];
    const float* rcR        = (const float*)d_in[1];
    const float* rcC        = (const float*)d_in[2];
    const float* winR       = (const float*)d_in[3];
    const float* hvac_gain  = (const float*)d_in[4];
    const float* W1         = (const float*)d_in[5];
    const float* B1         = (const float*)d_in[6];
    const float* W2         = (const float*)d_in[7];
    const float* B2         = (const float*)d_in[8];
    const float* int_gain   = (const float*)d_in[9];
    const float* direct_gain= (const float*)d_in[10];
    const float* abs_wall   = (const float*)d_in[11];
    const float* abs_roof   = (const float*)d_in[12];
    const float* zone_C_inv = (const float*)d_in[13];
    float* out = (float*)d_out;

    k_pre<<<1, 32>>>(rcR, rcC, winR, W1, B1, W2, B2,
                     int_gain, hvac_gain, direct_gain,
                     abs_wall, abs_roof, zone_C_inv);
    dim3 gA(B_LEN / 64, N_CH);
    kA<<<gA, 256>>>(X);
    k_scan<<<B_LEN / 64, 64>>>(X, rcR, rcC, winR, abs_wall, abs_roof,
                               zone_C_inv);
    dim3 ge(B_LEN / 64, T_LEN / 48);
    k_emit<<<ge, 256>>>(out);
}